// round 4
// baseline (speedup 1.0000x reference)
#include <cuda_runtime.h>
#include <cuda_bf16.h>
#include <math.h>
#include <stdint.h>

#define DIM 1024
#define NMAX 32768
#define MAXNORM (1.0f - 1e-5f)
#define MIN_NORM 1e-15f

// ---------------- GEMM tiling ----------------
#define BM 128
#define BN 256
#define BKE 32                      // bf16 k elements per stage (64B per row)
#define KITERS (DIM / BKE)          // 32
#define STAGES 4
// per-stage layout: Ah 8KB | Al 8KB | Bh 16KB | Bl 16KB
#define ST_AH 0
#define ST_AL 8192
#define ST_BH 16384
#define ST_BL 32768
#define STAGE_BYTES 49152
#define SMEM_BYTES (STAGES * STAGE_BYTES)   // 192KB

// ---------------- scratch (device globals) ----------------
__device__ float          g_mx[(size_t)NMAX * DIM];
__device__ __nv_bfloat16  g_ah[(size_t)NMAX * DIM];
__device__ __nv_bfloat16  g_al[(size_t)NMAX * DIM];
__device__ __nv_bfloat16  g_w1h[DIM * DIM], g_w1l[DIM * DIM];
__device__ __nv_bfloat16  g_w2h[DIM * DIM], g_w2l[DIM * DIM];
__device__ float          g_xn[NMAX];
__device__ float          g_hb[2][DIM];
__device__ float          g_y2[2];

// ---------------- PTX helpers ----------------
__device__ __forceinline__ uint32_t smem_u32(const void* p) {
    uint32_t a;
    asm("{ .reg .u64 t; cvta.to.shared.u64 t, %1; cvt.u32.u64 %0, t; }" : "=r"(a) : "l"(p));
    return a;
}
#define CP_ASYNC16(dst, src) \
    asm volatile("cp.async.cg.shared.global [%0], [%1], 16;" :: "r"(dst), "l"(src) : "memory")
#define CP_COMMIT() asm volatile("cp.async.commit_group;" ::: "memory")
#define CP_WAIT3()  asm volatile("cp.async.wait_group 3;" ::: "memory")

__device__ __forceinline__ void ldsm4(uint32_t* r, uint32_t addr) {
    asm volatile("ldmatrix.sync.aligned.m8n8.x4.shared.b16 {%0,%1,%2,%3}, [%4];"
                 : "=r"(r[0]), "=r"(r[1]), "=r"(r[2]), "=r"(r[3]) : "r"(addr));
}
__device__ __forceinline__ void mma16816(float* c, const uint32_t* a, uint32_t b0, uint32_t b1) {
    asm volatile("mma.sync.aligned.m16n8k16.row.col.f32.bf16.bf16.f32 "
                 "{%0,%1,%2,%3}, {%4,%5,%6,%7}, {%8,%9}, {%0,%1,%2,%3};"
                 : "+f"(c[0]), "+f"(c[1]), "+f"(c[2]), "+f"(c[3])
                 : "r"(a[0]), "r"(a[1]), "r"(a[2]), "r"(a[3]), "r"(b0), "r"(b1));
}

// ---------------- generic helpers ----------------
__device__ __forceinline__ float artanh_clip(float x) {
    const float lim = 1.0f - 1e-7f;
    x = fminf(fmaxf(x, -lim), lim);
    return atanhf(x);
}
__device__ __forceinline__ float blockReduceSum(float v) {
    __shared__ float sbuf[32];
    #pragma unroll
    for (int o = 16; o > 0; o >>= 1) v += __shfl_xor_sync(0xffffffffu, v, o);
    const int lane = threadIdx.x & 31;
    const int w    = threadIdx.x >> 5;
    if (lane == 0) sbuf[w] = v;
    __syncthreads();
    if (w == 0) {
        float t = (lane < 8) ? sbuf[lane] : 0.0f;
        #pragma unroll
        for (int o = 4; o > 0; o >>= 1) t += __shfl_xor_sync(0xffffffffu, t, o);
        if (lane == 0) sbuf[0] = t;
    }
    __syncthreads();
    float r = sbuf[0];
    __syncthreads();
    return r;
}
__device__ __forceinline__ void split1(float x, __nv_bfloat16& h, __nv_bfloat16& l) {
    h = __float2bfloat16(x);
    l = __float2bfloat16(x - __bfloat162float(h));
}

// ---------------- small kernels ----------------
__global__ __launch_bounds__(256)
void splitw_kernel(const float* __restrict__ W, __nv_bfloat16* __restrict__ H, __nv_bfloat16* __restrict__ L) {
    const size_t i = (size_t)blockIdx.x * 256 + threadIdx.x;
    float4 v = reinterpret_cast<const float4*>(W)[i];
    __nv_bfloat16 h[4], l[4];
    split1(v.x, h[0], l[0]); split1(v.y, h[1], l[1]);
    split1(v.z, h[2], l[2]); split1(v.w, h[3], l[3]);
    __nv_bfloat162 h01; h01.x = h[0]; h01.y = h[1];
    __nv_bfloat162 h23; h23.x = h[2]; h23.y = h[3];
    __nv_bfloat162 l01; l01.x = l[0]; l01.y = l[1];
    __nv_bfloat162 l23; l23.x = l[2]; l23.y = l[3];
    reinterpret_cast<__nv_bfloat162*>(H)[i * 2 + 0] = h01;
    reinterpret_cast<__nv_bfloat162*>(H)[i * 2 + 1] = h23;
    reinterpret_cast<__nv_bfloat162*>(L)[i * 2 + 0] = l01;
    reinterpret_cast<__nv_bfloat162*>(L)[i * 2 + 1] = l23;
}

__global__ __launch_bounds__(256)
void splitx_kernel(const float* __restrict__ X, __nv_bfloat16* __restrict__ H,
                   __nv_bfloat16* __restrict__ L, float* __restrict__ xn) {
    const int t = threadIdx.x;
    const size_t base = (size_t)blockIdx.x * DIM;
    float4 v = reinterpret_cast<const float4*>(X + base)[t];
    float s = blockReduceSum(v.x * v.x + v.y * v.y + v.z * v.z + v.w * v.w);
    if (t == 0) xn[blockIdx.x] = fmaxf(sqrtf(s), MIN_NORM);
    __nv_bfloat16 h[4], l[4];
    split1(v.x, h[0], l[0]); split1(v.y, h[1], l[1]);
    split1(v.z, h[2], l[2]); split1(v.w, h[3], l[3]);
    __nv_bfloat162 h01; h01.x = h[0]; h01.y = h[1];
    __nv_bfloat162 h23; h23.x = h[2]; h23.y = h[3];
    __nv_bfloat162 l01; l01.x = l[0]; l01.y = l[1];
    __nv_bfloat162 l23; l23.x = l[2]; l23.y = l[3];
    reinterpret_cast<__nv_bfloat162*>(H + base)[t * 2 + 0] = h01;
    reinterpret_cast<__nv_bfloat162*>(H + base)[t * 2 + 1] = h23;
    reinterpret_cast<__nv_bfloat162*>(L + base)[t * 2 + 0] = l01;
    reinterpret_cast<__nv_bfloat162*>(L + base)[t * 2 + 1] = l23;
}

__global__ __launch_bounds__(256)
void bias_kernel(const float* __restrict__ b, int layer) {
    const int t = threadIdx.x;
    float4 v = reinterpret_cast<const float4*>(b)[t];
    float w0 = v.x, w1 = v.y, w2 = v.z, w3 = v.w;
    float s = blockReduceSum(w0*w0 + w1*w1 + w2*w2 + w3*w3);
    float n = fmaxf(sqrtf(s), MIN_NORM);
    float sc = tanhf(n) / n;
    w0 *= sc; w1 *= sc; w2 *= sc; w3 *= sc;
    float s2 = blockReduceSum(w0*w0 + w1*w1 + w2*w2 + w3*w3);
    float n2 = fmaxf(sqrtf(s2), MIN_NORM);
    if (n2 > MAXNORM) { float f = MAXNORM / n2; w0*=f; w1*=f; w2*=f; w3*=f; }
    float s3 = blockReduceSum(w0*w0 + w1*w1 + w2*w2 + w3*w3);
    reinterpret_cast<float4*>(g_hb[layer])[t] = make_float4(w0, w1, w2, w3);
    if (t == 0) g_y2[layer] = s3;
}

// ---------------- HMMA bf16x3 GEMM: C[m,n] = sum_k A[m,k]*B[n,k] ----------------
// SMEM row layout: chunk(row, c) at row*64 + ((c ^ ((row>>1)&3))*16)
__global__ __launch_bounds__(256, 1)
void gemm3_kernel(const __nv_bfloat16* __restrict__ Ah, const __nv_bfloat16* __restrict__ Al,
                  const __nv_bfloat16* __restrict__ Bh, const __nv_bfloat16* __restrict__ Bl,
                  float* __restrict__ C) {
    extern __shared__ char smem[];
    const uint32_t s32 = smem_u32(smem);

    const int tid = threadIdx.x;
    const int wid = tid >> 5;
    const int lid = tid & 31;
    const int m0 = blockIdx.y * BM;
    const int n0 = blockIdx.x * BN;
    const int warpM = (wid & 1) * 64;   // 2 warps along M
    const int warpN = (wid >> 1) * 64;  // 4 warps along N

    // ---- loader mapping ----
    const int row0 = tid >> 2;          // 0..63
    const int cc   = tid & 3;
    uint32_t offR[4];
    #pragma unroll
    for (int q = 0; q < 4; ++q) {
        const int r = row0 + q * 64;
        offR[q] = (uint32_t)(r * 64 + ((cc ^ ((r >> 1) & 3)) * 16));
    }
    const __nv_bfloat16* aH0 = Ah + (size_t)(m0 + row0) * DIM + cc * 8;
    const __nv_bfloat16* aL0 = Al + (size_t)(m0 + row0) * DIM + cc * 8;
    const __nv_bfloat16* bH0 = Bh + (size_t)(n0 + row0) * DIM + cc * 8;
    const __nv_bfloat16* bL0 = Bl + (size_t)(n0 + row0) * DIM + cc * 8;
    const size_t rs = (size_t)64 * DIM;

    // ---- ldmatrix lane offsets ----
    uint32_t ofsA[4][2], ofsB[4][2];
    {
        const int lrow = (lid & 7) + ((lid >> 3) & 1) * 8;
        const int lchk = lid >> 4;   // 0/1
        #pragma unroll
        for (int f = 0; f < 4; ++f)
            #pragma unroll
            for (int ks = 0; ks < 2; ++ks) {
                int rA = warpM + f * 16 + lrow;
                int rB = warpN + f * 16 + lrow;
                int c  = 2 * ks + lchk;
                ofsA[f][ks] = (uint32_t)(rA * 64 + ((c ^ ((rA >> 1) & 3)) * 16));
                ofsB[f][ks] = (uint32_t)(rB * 64 + ((c ^ ((rB >> 1) & 3)) * 16));
            }
    }

    float acc[4][8][4];
    #pragma unroll
    for (int i = 0; i < 4; ++i)
        #pragma unroll
        for (int j = 0; j < 8; ++j)
            #pragma unroll
            for (int q = 0; q < 4; ++q) acc[i][j][q] = 0.0f;

    auto issue = [&](int kt) {
        const uint32_t sb = s32 + (kt % STAGES) * STAGE_BYTES;
        const size_t ko = (size_t)kt * BKE;
        CP_ASYNC16(sb + ST_AH + offR[0], aH0 + ko);
        CP_ASYNC16(sb + ST_AH + offR[1], aH0 + rs + ko);
        CP_ASYNC16(sb + ST_AL + offR[0], aL0 + ko);
        CP_ASYNC16(sb + ST_AL + offR[1], aL0 + rs + ko);
        #pragma unroll
        for (int q = 0; q < 4; ++q) {
            CP_ASYNC16(sb + ST_BH + offR[q], bH0 + q * rs + ko);
            CP_ASYNC16(sb + ST_BL + offR[q], bL0 + q * rs + ko);
        }
    };

    // prologue: stages 0..2
    #pragma unroll
    for (int s = 0; s < STAGES - 1; ++s) { issue(s); CP_COMMIT(); }

    for (int kt = 0; kt < KITERS; ++kt) {
        if (kt + STAGES - 1 < KITERS) issue(kt + STAGES - 1);
        CP_COMMIT();                 // constant group accounting (dummy at tail)
        CP_WAIT3();
        __syncthreads();

        const uint32_t sA = s32 + (kt % STAGES) * STAGE_BYTES;
        #pragma unroll
        for (int ks = 0; ks < 2; ++ks) {
            uint32_t ahf[4][4], alf[4][4];
            #pragma unroll
            for (int f = 0; f < 4; ++f) {
                ldsm4(ahf[f], sA + ST_AH + ofsA[f][ks]);
                ldsm4(alf[f], sA + ST_AL + ofsA[f][ks]);
            }
            #pragma unroll
            for (int p = 0; p < 4; ++p) {
                uint32_t bh[4], bl[4];
                ldsm4(bh, sA + ST_BH + ofsB[p][ks]);
                ldsm4(bl, sA + ST_BL + ofsB[p][ks]);
                #pragma unroll
                for (int mf = 0; mf < 4; ++mf) {
                    mma16816(acc[mf][2*p],   ahf[mf], bh[0], bh[2]);
                    mma16816(acc[mf][2*p],   ahf[mf], bl[0], bl[2]);
                    mma16816(acc[mf][2*p],   alf[mf], bh[0], bh[2]);
                    mma16816(acc[mf][2*p+1], ahf[mf], bh[1], bh[3]);
                    mma16816(acc[mf][2*p+1], ahf[mf], bl[1], bl[3]);
                    mma16816(acc[mf][2*p+1], alf[mf], bh[1], bh[3]);
                }
            }
        }
        __syncthreads();
    }

    // ---- epilogue: direct stores ----
    #pragma unroll
    for (int mf = 0; mf < 4; ++mf) {
        #pragma unroll
        for (int nf = 0; nf < 8; ++nf) {
            const int r   = m0 + warpM + mf * 16 + (lid >> 2);
            const int col = n0 + warpN + nf * 8 + (lid & 3) * 2;
            float2 v0 = make_float2(acc[mf][nf][0], acc[mf][nf][1]);
            float2 v1 = make_float2(acc[mf][nf][2], acc[mf][nf][3]);
            *reinterpret_cast<float2*>(&C[(size_t)r * DIM + col])       = v0;
            *reinterpret_cast<float2*>(&C[(size_t)(r + 8) * DIM + col]) = v1;
        }
    }
}

// ---------------- fused per-row epilogue ----------------
template<bool SPLIT>
__global__ __launch_bounds__(256)
void rowpost_kernel(const float* __restrict__ MX, const float* __restrict__ xnv,
                    float* __restrict__ OUT,
                    __nv_bfloat16* __restrict__ OH, __nv_bfloat16* __restrict__ OL,
                    float* __restrict__ xnout, int layer) {
    const int t = threadIdx.x;
    const size_t base = (size_t)blockIdx.x * DIM;

    float4 v = reinterpret_cast<const float4*>(MX + base)[t];
    float w[4] = {v.x, v.y, v.z, v.w};
    const float xn = xnv[blockIdx.x];

    float r1 = blockReduceSum(w[0]*w[0] + w[1]*w[1] + w[2]*w[2] + w[3]*w[3]);
    const bool allzero = (r1 == 0.0f);
    const float mxn = fmaxf(sqrtf(r1), MIN_NORM);
    const float arg = (mxn / xn) * artanh_clip(xn);
    float sres = tanhf(arg) / mxn;
    if (allzero) sres = 0.0f;
    #pragma unroll
    for (int i = 0; i < 4; ++i) w[i] *= sres;

    {
        float s = blockReduceSum(w[0]*w[0] + w[1]*w[1] + w[2]*w[2] + w[3]*w[3]);
        float n = fmaxf(sqrtf(s), MIN_NORM);
        if (n > MAXNORM) { float f = MAXNORM / n; w[0]*=f; w[1]*=f; w[2]*=f; w[3]*=f; }
    }
    {
        float4 hv = reinterpret_cast<const float4*>(g_hb[layer])[t];
        float h[4] = {hv.x, hv.y, hv.z, hv.w};
        float x2 = blockReduceSum(w[0]*w[0] + w[1]*w[1] + w[2]*w[2] + w[3]*w[3]);
        float xy = blockReduceSum(w[0]*h[0] + w[1]*h[1] + w[2]*h[2] + w[3]*h[3]);
        float y2 = g_y2[layer];
        float alpha = 1.0f + 2.0f * xy + y2;
        float beta  = 1.0f - x2;
        float inv   = 1.0f / fmaxf(1.0f + 2.0f * xy + x2 * y2, MIN_NORM);
        #pragma unroll
        for (int i = 0; i < 4; ++i) w[i] = (alpha * w[i] + beta * h[i]) * inv;
    }
    {
        float s = blockReduceSum(w[0]*w[0] + w[1]*w[1] + w[2]*w[2] + w[3]*w[3]);
        float n = fmaxf(sqrtf(s), MIN_NORM);
        if (n > MAXNORM) { float f = MAXNORM / n; w[0]*=f; w[1]*=f; w[2]*=f; w[3]*=f; }
    }
    {
        float s = blockReduceSum(w[0]*w[0] + w[1]*w[1] + w[2]*w[2] + w[3]*w[3]);
        float n = fmaxf(sqrtf(s), MIN_NORM);
        if (n > MAXNORM) { float f = MAXNORM / n; w[0]*=f; w[1]*=f; w[2]*=f; w[3]*=f; }
    }
    {
        float s = blockReduceSum(w[0]*w[0] + w[1]*w[1] + w[2]*w[2] + w[3]*w[3]);
        float n = fmaxf(sqrtf(s), MIN_NORM);
        float sl = artanh_clip(n) / n;
        #pragma unroll
        for (int i = 0; i < 4; ++i) w[i] = tanhf(sl * w[i]);
    }
    {
        float s = blockReduceSum(w[0]*w[0] + w[1]*w[1] + w[2]*w[2] + w[3]*w[3]);
        float tn = fmaxf(sqrtf(s), MIN_NORM);
        float se = tanhf(tn) / tn;
        #pragma unroll
        for (int i = 0; i < 4; ++i) w[i] *= se;
    }
    float nfin;
    {
        float s = blockReduceSum(w[0]*w[0] + w[1]*w[1] + w[2]*w[2] + w[3]*w[3]);
        float n = fmaxf(sqrtf(s), MIN_NORM);
        nfin = fminf(n, MAXNORM);
        if (n > MAXNORM) { float f = MAXNORM / n; w[0]*=f; w[1]*=f; w[2]*=f; w[3]*=f; }
    }

    if (SPLIT) {
        __nv_bfloat16 h[4], l[4];
        #pragma unroll
        for (int i = 0; i < 4; ++i) split1(w[i], h[i], l[i]);
        __nv_bfloat162 h01; h01.x = h[0]; h01.y = h[1];
        __nv_bfloat162 h23; h23.x = h[2]; h23.y = h[3];
        __nv_bfloat162 l01; l01.x = l[0]; l01.y = l[1];
        __nv_bfloat162 l23; l23.x = l[2]; l23.y = l[3];
        reinterpret_cast<__nv_bfloat162*>(OH + base)[t * 2 + 0] = h01;
        reinterpret_cast<__nv_bfloat162*>(OH + base)[t * 2 + 1] = h23;
        reinterpret_cast<__nv_bfloat162*>(OL + base)[t * 2 + 0] = l01;
        reinterpret_cast<__nv_bfloat162*>(OL + base)[t * 2 + 1] = l23;
        if (t == 0) xnout[blockIdx.x] = fmaxf(nfin, MIN_NORM);
    } else {
        reinterpret_cast<float4*>(OUT + base)[t] = make_float4(w[0], w[1], w[2], w[3]);
    }
}

// ---------------- launch ----------------
extern "C" void kernel_launch(void* const* d_in, const int* in_sizes, int n_in,
                              void* d_out, int out_size) {
    const float* x  = (const float*)d_in[0];
    const float* W1 = (const float*)d_in[1];
    const float* b1 = (const float*)d_in[2];
    const float* W2 = (const float*)d_in[3];
    const float* b2 = (const float*)d_in[4];
    float* out = (float*)d_out;

    const int N = in_sizes[0] / DIM;

    float *mx = nullptr, *xn = nullptr;
    __nv_bfloat16 *ah, *al, *w1h, *w1l, *w2h, *w2l;
    cudaGetSymbolAddress((void**)&mx,  g_mx);
    cudaGetSymbolAddress((void**)&xn,  g_xn);
    cudaGetSymbolAddress((void**)&ah,  g_ah);
    cudaGetSymbolAddress((void**)&al,  g_al);
    cudaGetSymbolAddress((void**)&w1h, g_w1h);
    cudaGetSymbolAddress((void**)&w1l, g_w1l);
    cudaGetSymbolAddress((void**)&w2h, g_w2h);
    cudaGetSymbolAddress((void**)&w2l, g_w2l);

    cudaFuncSetAttribute(gemm3_kernel, cudaFuncAttributeMaxDynamicSharedMemorySize, SMEM_BYTES);

    const dim3 ggrid(DIM / BN, N / BM);
    const int wgrid = (DIM * DIM) / (4 * 256);

    splitw_kernel<<<wgrid, 256>>>(W1, w1h, w1l);
    splitw_kernel<<<wgrid, 256>>>(W2, w2h, w2l);
    bias_kernel<<<1, 256>>>(b1, 0);
    bias_kernel<<<1, 256>>>(b2, 1);

    // layer 1
    splitx_kernel<<<N, 256>>>(x, ah, al, xn);
    gemm3_kernel<<<ggrid, 256, SMEM_BYTES>>>(ah, al, w1h, w1l, mx);
    rowpost_kernel<true><<<N, 256>>>(mx, xn, nullptr, ah, al, xn, 0);

    // layer 2
    gemm3_kernel<<<ggrid, 256, SMEM_BYTES>>>(ah, al, w2h, w2l, out);
    rowpost_kernel<false><<<N, 256>>>(out, xn, out, nullptr, nullptr, nullptr, 1);
}

// round 5
// speedup vs baseline: 1.3706x; 1.3706x over previous
#include <cuda_runtime.h>
#include <cuda_fp16.h>
#include <math.h>
#include <stdint.h>

#define DIM 1024
#define NMAX 32768
#define MAXNORM (1.0f - 1e-5f)
#define MIN_NORM 1e-15f

#define ASCALE  1024.0f      // A pre-scale (keeps Al in fp16 normal range)
#define AISCALE (1.0f / 1024.0f)

// ---------------- GEMM tiling (R3-proven config) ----------------
#define BM 128
#define BN 128
#define BKE 32                     // fp16 k elements per stage (64 bytes per row)
#define KITERS (DIM / BKE)         // 32
// per-stage layout: Ah 8KB | Al 8KB | B 8KB
#define ST_AH 0
#define ST_AL 8192
#define ST_B  16384
#define STAGE_BYTES 24576
#define SMEM_BYTES (2 * STAGE_BYTES)   // 48KB, 2 CTAs/SM

// ---------------- scratch (device globals) ----------------
__device__ float   g_mx[(size_t)NMAX * DIM];   // fp32 GEMM output
__device__ __half  g_ah[(size_t)NMAX * DIM];   // activation hi (scaled by 1024)
__device__ __half  g_al[(size_t)NMAX * DIM];   // activation lo (scaled by 1024)
__device__ __half  g_w1[DIM * DIM];
__device__ __half  g_w2[DIM * DIM];
__device__ float   g_xn[NMAX];
__device__ float   g_hb[2][DIM];
__device__ float   g_y2[2];

// ---------------- PTX helpers ----------------
__device__ __forceinline__ uint32_t smem_u32(const void* p) {
    uint32_t a;
    asm("{ .reg .u64 t; cvta.to.shared.u64 t, %1; cvt.u32.u64 %0, t; }" : "=r"(a) : "l"(p));
    return a;
}
#define CP_ASYNC16(dst, src) \
    asm volatile("cp.async.cg.shared.global [%0], [%1], 16;" :: "r"(dst), "l"(src) : "memory")
#define CP_COMMIT() asm volatile("cp.async.commit_group;" ::: "memory")
#define CP_WAIT1()  asm volatile("cp.async.wait_group 1;" ::: "memory")
#define CP_WAIT0()  asm volatile("cp.async.wait_group 0;" ::: "memory")

__device__ __forceinline__ void ldsm4(uint32_t* r, uint32_t addr) {
    asm volatile("ldmatrix.sync.aligned.m8n8.x4.shared.b16 {%0,%1,%2,%3}, [%4];"
                 : "=r"(r[0]), "=r"(r[1]), "=r"(r[2]), "=r"(r[3]) : "r"(addr));
}
__device__ __forceinline__ void mma16816(float* c, const uint32_t* a, uint32_t b0, uint32_t b1) {
    asm volatile("mma.sync.aligned.m16n8k16.row.col.f32.f16.f16.f32 "
                 "{%0,%1,%2,%3}, {%4,%5,%6,%7}, {%8,%9}, {%0,%1,%2,%3};"
                 : "+f"(c[0]), "+f"(c[1]), "+f"(c[2]), "+f"(c[3])
                 : "r"(a[0]), "r"(a[1]), "r"(a[2]), "r"(a[3]), "r"(b0), "r"(b1));
}

// ---------------- generic helpers ----------------
__device__ __forceinline__ float artanh_clip(float x) {
    const float lim = 1.0f - 1e-7f;
    x = fminf(fmaxf(x, -lim), lim);
    return atanhf(x);
}
__device__ __forceinline__ float blockReduceSum(float v) {
    __shared__ float sbuf[32];
    #pragma unroll
    for (int o = 16; o > 0; o >>= 1) v += __shfl_xor_sync(0xffffffffu, v, o);
    const int lane = threadIdx.x & 31;
    const int w    = threadIdx.x >> 5;
    if (lane == 0) sbuf[w] = v;
    __syncthreads();
    if (w == 0) {
        float t = (lane < 8) ? sbuf[lane] : 0.0f;
        #pragma unroll
        for (int o = 4; o > 0; o >>= 1) t += __shfl_xor_sync(0xffffffffu, t, o);
        if (lane == 0) sbuf[0] = t;
    }
    __syncthreads();
    float r = sbuf[0];
    __syncthreads();
    return r;
}
// split scaled value into fp16 hi/lo:  x*1024 = hi + lo (both fp16-normal)
__device__ __forceinline__ void split1h(float x, __half& h, __half& l) {
    const float xs = x * ASCALE;
    h = __float2half(xs);
    l = __float2half(xs - __half2float(h));
}

// ---------------- small kernels ----------------
// weights: fp32 -> fp16 (single array, unscaled)
__global__ __launch_bounds__(256)
void splitw_kernel(const float* __restrict__ W, __half* __restrict__ H) {
    const size_t i = (size_t)blockIdx.x * 256 + threadIdx.x;
    float4 v = reinterpret_cast<const float4*>(W)[i];
    __half2 a, b;
    a.x = __float2half(v.x); a.y = __float2half(v.y);
    b.x = __float2half(v.z); b.y = __float2half(v.w);
    reinterpret_cast<__half2*>(H)[i * 2 + 0] = a;
    reinterpret_cast<__half2*>(H)[i * 2 + 1] = b;
}

// activations: fp32 -> scaled fp16 hi/lo splits + row norm
__global__ __launch_bounds__(256)
void splitx_kernel(const float* __restrict__ X, __half* __restrict__ H,
                   __half* __restrict__ L, float* __restrict__ xn) {
    const int t = threadIdx.x;
    const size_t base = (size_t)blockIdx.x * DIM;
    float4 v = reinterpret_cast<const float4*>(X + base)[t];
    float s = blockReduceSum(v.x * v.x + v.y * v.y + v.z * v.z + v.w * v.w);
    if (t == 0) xn[blockIdx.x] = fmaxf(sqrtf(s), MIN_NORM);
    __half h[4], l[4];
    split1h(v.x, h[0], l[0]); split1h(v.y, h[1], l[1]);
    split1h(v.z, h[2], l[2]); split1h(v.w, h[3], l[3]);
    __half2 h01; h01.x = h[0]; h01.y = h[1];
    __half2 h23; h23.x = h[2]; h23.y = h[3];
    __half2 l01; l01.x = l[0]; l01.y = l[1];
    __half2 l23; l23.x = l[2]; l23.y = l[3];
    reinterpret_cast<__half2*>(H + base)[t * 2 + 0] = h01;
    reinterpret_cast<__half2*>(H + base)[t * 2 + 1] = h23;
    reinterpret_cast<__half2*>(L + base)[t * 2 + 0] = l01;
    reinterpret_cast<__half2*>(L + base)[t * 2 + 1] = l23;
}

__global__ __launch_bounds__(256)
void bias_kernel(const float* __restrict__ b, int layer) {
    const int t = threadIdx.x;
    float4 v = reinterpret_cast<const float4*>(b)[t];
    float w0 = v.x, w1 = v.y, w2 = v.z, w3 = v.w;
    float s = blockReduceSum(w0*w0 + w1*w1 + w2*w2 + w3*w3);
    float n = fmaxf(sqrtf(s), MIN_NORM);
    float sc = tanhf(n) / n;
    w0 *= sc; w1 *= sc; w2 *= sc; w3 *= sc;
    float s2 = blockReduceSum(w0*w0 + w1*w1 + w2*w2 + w3*w3);
    float n2 = fmaxf(sqrtf(s2), MIN_NORM);
    if (n2 > MAXNORM) { float f = MAXNORM / n2; w0*=f; w1*=f; w2*=f; w3*=f; }
    float s3 = blockReduceSum(w0*w0 + w1*w1 + w2*w2 + w3*w3);
    reinterpret_cast<float4*>(g_hb[layer])[t] = make_float4(w0, w1, w2, w3);
    if (t == 0) g_y2[layer] = s3;
}

// ---------------- HMMA fp16x2 GEMM: C[m,n] = sum_k A[m,k]*B[n,k] ----------------
// A scaled by 1024 (hi+lo), B fp16; epilogue descales. R3-proven tiling.
// SMEM chunk layout per array: chunk(row, c) at row*64 + ((c ^ ((row>>1)&3))*16)
__global__ __launch_bounds__(256, 2)
void gemm2_kernel(const __half* __restrict__ Ah, const __half* __restrict__ Al,
                  const __half* __restrict__ B, float* __restrict__ C) {
    extern __shared__ char smem[];
    const uint32_t s32 = smem_u32(smem);

    const int tid = threadIdx.x;
    const int wid = tid >> 5;
    const int lid = tid & 31;
    const int m0 = blockIdx.y * BM;
    const int n0 = blockIdx.x * BN;
    const int warpM = (wid & 3) * 32;
    const int warpN = (wid >> 2) * 64;

    // ---- loader mapping: thread handles chunks i and i+256 of each array ----
    const int row0 = tid >> 2;           // 0..63
    const int cc   = tid & 3;
    const uint32_t off0 = (uint32_t)(row0 * 64 + ((cc ^ ((row0 >> 1) & 3)) * 16));
    const int row1 = row0 + 64;
    const uint32_t off1 = (uint32_t)(row1 * 64 + ((cc ^ ((row1 >> 1) & 3)) * 16));

    const __half* aH0 = Ah + (size_t)(m0 + row0) * DIM + cc * 8;
    const __half* aL0 = Al + (size_t)(m0 + row0) * DIM + cc * 8;
    const __half* b0  = B  + (size_t)(n0 + row0) * DIM + cc * 8;
    const size_t rstep = (size_t)64 * DIM;

    // ---- ldmatrix lane offsets ----
    uint32_t ofsA[2][2], ofsB[4][2];
    {
        const int lrow = (lid & 7) + ((lid >> 3) & 1) * 8;
        const int lchk = lid >> 4;       // 0/1
        #pragma unroll
        for (int mf = 0; mf < 2; ++mf)
            #pragma unroll
            for (int ks = 0; ks < 2; ++ks) {
                int r = warpM + mf * 16 + lrow;
                int c = 2 * ks + lchk;
                ofsA[mf][ks] = (uint32_t)(r * 64 + ((c ^ ((r >> 1) & 3)) * 16));
            }
        #pragma unroll
        for (int p = 0; p < 4; ++p)
            #pragma unroll
            for (int ks = 0; ks < 2; ++ks) {
                int r = warpN + p * 16 + lrow;
                int c = 2 * ks + lchk;
                ofsB[p][ks] = (uint32_t)(r * 64 + ((c ^ ((r >> 1) & 3)) * 16));
            }
    }

    float acc[2][8][4];
    #pragma unroll
    for (int i = 0; i < 2; ++i)
        #pragma unroll
        for (int j = 0; j < 8; ++j)
            #pragma unroll
            for (int q = 0; q < 4; ++q) acc[i][j][q] = 0.0f;

    auto issue = [&](int kt) {
        const uint32_t sb = s32 + (kt & 1) * STAGE_BYTES;
        const size_t ko = (size_t)kt * BKE;
        CP_ASYNC16(sb + ST_AH + off0, aH0 + ko);
        CP_ASYNC16(sb + ST_AH + off1, aH0 + rstep + ko);
        CP_ASYNC16(sb + ST_AL + off0, aL0 + ko);
        CP_ASYNC16(sb + ST_AL + off1, aL0 + rstep + ko);
        CP_ASYNC16(sb + ST_B  + off0, b0  + ko);
        CP_ASYNC16(sb + ST_B  + off1, b0  + rstep + ko);
    };

    issue(0); CP_COMMIT();
    for (int kt = 0; kt < KITERS; ++kt) {
        if (kt + 1 < KITERS) { issue(kt + 1); CP_COMMIT(); CP_WAIT1(); }
        else                 { CP_WAIT0(); }
        __syncthreads();

        const uint32_t sA = s32 + (kt & 1) * STAGE_BYTES;
        #pragma unroll
        for (int ks = 0; ks < 2; ++ks) {
            uint32_t ahf[2][4], alf[2][4];
            ldsm4(ahf[0], sA + ST_AH + ofsA[0][ks]);
            ldsm4(ahf[1], sA + ST_AH + ofsA[1][ks]);
            ldsm4(alf[0], sA + ST_AL + ofsA[0][ks]);
            ldsm4(alf[1], sA + ST_AL + ofsA[1][ks]);
            #pragma unroll
            for (int p = 0; p < 4; ++p) {
                uint32_t bh[4];
                ldsm4(bh, sA + ST_B + ofsB[p][ks]);
                #pragma unroll
                for (int mf = 0; mf < 2; ++mf) {
                    mma16816(acc[mf][2*p],   ahf[mf], bh[0], bh[2]);
                    mma16816(acc[mf][2*p],   alf[mf], bh[0], bh[2]);
                    mma16816(acc[mf][2*p+1], ahf[mf], bh[1], bh[3]);
                    mma16816(acc[mf][2*p+1], alf[mf], bh[1], bh[3]);
                }
            }
        }
        __syncthreads();
    }

    // ---- epilogue: descale + direct stores ----
    #pragma unroll
    for (int mf = 0; mf < 2; ++mf) {
        #pragma unroll
        for (int nf = 0; nf < 8; ++nf) {
            const int r   = m0 + warpM + mf * 16 + (lid >> 2);
            const int col = n0 + warpN + nf * 8 + (lid & 3) * 2;
            float2 v0 = make_float2(acc[mf][nf][0] * AISCALE, acc[mf][nf][1] * AISCALE);
            float2 v1 = make_float2(acc[mf][nf][2] * AISCALE, acc[mf][nf][3] * AISCALE);
            *reinterpret_cast<float2*>(&C[(size_t)r * DIM + col])       = v0;
            *reinterpret_cast<float2*>(&C[(size_t)(r + 8) * DIM + col]) = v1;
        }
    }
}

// ---------------- fused per-row epilogue ----------------
template<bool SPLIT>
__global__ __launch_bounds__(256)
void rowpost_kernel(const float* __restrict__ MX, const float* __restrict__ xnv,
                    float* __restrict__ OUT,
                    __half* __restrict__ OH, __half* __restrict__ OL,
                    float* __restrict__ xnout, int layer) {
    const int t = threadIdx.x;
    const size_t base = (size_t)blockIdx.x * DIM;

    float4 v = reinterpret_cast<const float4*>(MX + base)[t];
    float w[4] = {v.x, v.y, v.z, v.w};
    const float xn = xnv[blockIdx.x];

    // gyro_matvec tail
    float r1 = blockReduceSum(w[0]*w[0] + w[1]*w[1] + w[2]*w[2] + w[3]*w[3]);
    const bool allzero = (r1 == 0.0f);
    const float mxn = fmaxf(sqrtf(r1), MIN_NORM);
    const float arg = (mxn / xn) * artanh_clip(xn);
    float sres = tanhf(arg) / mxn;
    if (allzero) sres = 0.0f;
    #pragma unroll
    for (int i = 0; i < 4; ++i) w[i] *= sres;

    // proj
    {
        float s = blockReduceSum(w[0]*w[0] + w[1]*w[1] + w[2]*w[2] + w[3]*w[3]);
        float n = fmaxf(sqrtf(s), MIN_NORM);
        if (n > MAXNORM) { float f = MAXNORM / n; w[0]*=f; w[1]*=f; w[2]*=f; w[3]*=f; }
    }
    // gyro_add(hyp_bias)
    {
        float4 hv = reinterpret_cast<const float4*>(g_hb[layer])[t];
        float h[4] = {hv.x, hv.y, hv.z, hv.w};
        float x2 = blockReduceSum(w[0]*w[0] + w[1]*w[1] + w[2]*w[2] + w[3]*w[3]);
        float xy = blockReduceSum(w[0]*h[0] + w[1]*h[1] + w[2]*h[2] + w[3]*h[3]);
        float y2 = g_y2[layer];
        float alpha = 1.0f + 2.0f * xy + y2;
        float beta  = 1.0f - x2;
        float inv   = 1.0f / fmaxf(1.0f + 2.0f * xy + x2 * y2, MIN_NORM);
        #pragma unroll
        for (int i = 0; i < 4; ++i) w[i] = (alpha * w[i] + beta * h[i]) * inv;
    }
    // proj (end of hyp_linear)
    {
        float s = blockReduceSum(w[0]*w[0] + w[1]*w[1] + w[2]*w[2] + w[3]*w[3]);
        float n = fmaxf(sqrtf(s), MIN_NORM);
        if (n > MAXNORM) { float f = MAXNORM / n; w[0]*=f; w[1]*=f; w[2]*=f; w[3]*=f; }
    }
    // hyp_tanh_act: proj
    {
        float s = blockReduceSum(w[0]*w[0] + w[1]*w[1] + w[2]*w[2] + w[3]*w[3]);
        float n = fmaxf(sqrtf(s), MIN_NORM);
        if (n > MAXNORM) { float f = MAXNORM / n; w[0]*=f; w[1]*=f; w[2]*=f; w[3]*=f; }
    }
    // logmap0 + tanh
    {
        float s = blockReduceSum(w[0]*w[0] + w[1]*w[1] + w[2]*w[2] + w[3]*w[3]);
        float n = fmaxf(sqrtf(s), MIN_NORM);
        float sl = artanh_clip(n) / n;
        #pragma unroll
        for (int i = 0; i < 4; ++i) w[i] = tanhf(sl * w[i]);
    }
    // expmap0
    {
        float s = blockReduceSum(w[0]*w[0] + w[1]*w[1] + w[2]*w[2] + w[3]*w[3]);
        float tn = fmaxf(sqrtf(s), MIN_NORM);
        float se = tanhf(tn) / tn;
        #pragma unroll
        for (int i = 0; i < 4; ++i) w[i] *= se;
    }
    // final proj (+ next-layer norm)
    float nfin;
    {
        float s = blockReduceSum(w[0]*w[0] + w[1]*w[1] + w[2]*w[2] + w[3]*w[3]);
        float n = fmaxf(sqrtf(s), MIN_NORM);
        nfin = fminf(n, MAXNORM);
        if (n > MAXNORM) { float f = MAXNORM / n; w[0]*=f; w[1]*=f; w[2]*=f; w[3]*=f; }
    }

    if (SPLIT) {
        __half h[4], l[4];
        #pragma unroll
        for (int i = 0; i < 4; ++i) split1h(w[i], h[i], l[i]);
        __half2 h01; h01.x = h[0]; h01.y = h[1];
        __half2 h23; h23.x = h[2]; h23.y = h[3];
        __half2 l01; l01.x = l[0]; l01.y = l[1];
        __half2 l23; l23.x = l[2]; l23.y = l[3];
        reinterpret_cast<__half2*>(OH + base)[t * 2 + 0] = h01;
        reinterpret_cast<__half2*>(OH + base)[t * 2 + 1] = h23;
        reinterpret_cast<__half2*>(OL + base)[t * 2 + 0] = l01;
        reinterpret_cast<__half2*>(OL + base)[t * 2 + 1] = l23;
        if (t == 0) xnout[blockIdx.x] = fmaxf(nfin, MIN_NORM);
    } else {
        reinterpret_cast<float4*>(OUT + base)[t] = make_float4(w[0], w[1], w[2], w[3]);
    }
}

// ---------------- launch ----------------
extern "C" void kernel_launch(void* const* d_in, const int* in_sizes, int n_in,
                              void* d_out, int out_size) {
    const float* x  = (const float*)d_in[0];
    const float* W1 = (const float*)d_in[1];
    const float* b1 = (const float*)d_in[2];
    const float* W2 = (const float*)d_in[3];
    const float* b2 = (const float*)d_in[4];
    float* out = (float*)d_out;

    const int N = in_sizes[0] / DIM;

    float *mx = nullptr, *xn = nullptr;
    __half *ah, *al, *w1, *w2;
    cudaGetSymbolAddress((void**)&mx, g_mx);
    cudaGetSymbolAddress((void**)&xn, g_xn);
    cudaGetSymbolAddress((void**)&ah, g_ah);
    cudaGetSymbolAddress((void**)&al, g_al);
    cudaGetSymbolAddress((void**)&w1, g_w1);
    cudaGetSymbolAddress((void**)&w2, g_w2);

    cudaFuncSetAttribute(gemm2_kernel, cudaFuncAttributeMaxDynamicSharedMemorySize, SMEM_BYTES);

    const dim3 ggrid(DIM / BN, N / BM);
    const int wgrid = (DIM * DIM) / (4 * 256);

    splitw_kernel<<<wgrid, 256>>>(W1, w1);
    splitw_kernel<<<wgrid, 256>>>(W2, w2);
    bias_kernel<<<1, 256>>>(b1, 0);
    bias_kernel<<<1, 256>>>(b2, 1);

    // layer 1
    splitx_kernel<<<N, 256>>>(x, ah, al, xn);
    gemm2_kernel<<<ggrid, 256, SMEM_BYTES>>>(ah, al, w1, mx);
    rowpost_kernel<true><<<N, 256>>>(mx, xn, nullptr, ah, al, xn, 0);

    // layer 2
    gemm2_kernel<<<ggrid, 256, SMEM_BYTES>>>(ah, al, w2, out);
    rowpost_kernel<false><<<N, 256>>>(out, xn, out, nullptr, nullptr, nullptr, 1);
}

// round 6
// speedup vs baseline: 1.4366x; 1.0481x over previous
#include <cuda_runtime.h>
#include <cuda_fp16.h>
#include <math.h>
#include <stdint.h>

#define DIM 1024
#define NMAX 32768
#define MAXNORM (1.0f - 1e-5f)
#define MIN_NORM 1e-15f

#define ASCALE  1024.0f      // A pre-scale (keeps Al in fp16 normal range)
#define AISCALE (1.0f / 1024.0f)

// ---------------- GEMM tiling ----------------
#define BM 128
#define BN 128
#define BKE 32                     // fp16 k elements per stage (64 bytes per row)
#define KITERS (DIM / BKE)         // 32
#define STAGES 3
// per-stage layout: Ah 8KB | Al 8KB | B 8KB
#define ST_AH 0
#define ST_AL 8192
#define ST_B  16384
#define STAGE_BYTES 24576
#define SMEM_BYTES (STAGES * STAGE_BYTES)   // 72KB, 2 CTAs/SM

// ---------------- scratch (device globals) ----------------
__device__ float   g_mx[(size_t)NMAX * DIM];   // fp32 GEMM output
__device__ __half  g_ah[(size_t)NMAX * DIM];   // activation hi (scaled by 1024)
__device__ __half  g_al[(size_t)NMAX * DIM];   // activation lo (scaled by 1024)
__device__ __half  g_w1[DIM * DIM];
__device__ __half  g_w2[DIM * DIM];
__device__ float   g_xn[NMAX];
__device__ float   g_hb[2][DIM];
__device__ float   g_y2[2];

// ---------------- PTX helpers ----------------
__device__ __forceinline__ uint32_t smem_u32(const void* p) {
    uint32_t a;
    asm("{ .reg .u64 t; cvta.to.shared.u64 t, %1; cvt.u32.u64 %0, t; }" : "=r"(a) : "l"(p));
    return a;
}
#define CP_ASYNC16(dst, src) \
    asm volatile("cp.async.cg.shared.global [%0], [%1], 16;" :: "r"(dst), "l"(src) : "memory")
#define CP_COMMIT() asm volatile("cp.async.commit_group;" ::: "memory")
#define CP_WAIT1()  asm volatile("cp.async.wait_group 1;" ::: "memory")

__device__ __forceinline__ void ldsm4(uint32_t* r, uint32_t addr) {
    asm volatile("ldmatrix.sync.aligned.m8n8.x4.shared.b16 {%0,%1,%2,%3}, [%4];"
                 : "=r"(r[0]), "=r"(r[1]), "=r"(r[2]), "=r"(r[3]) : "r"(addr));
}
__device__ __forceinline__ void mma16816(float* c, const uint32_t* a, uint32_t b0, uint32_t b1) {
    asm volatile("mma.sync.aligned.m16n8k16.row.col.f32.f16.f16.f32 "
                 "{%0,%1,%2,%3}, {%4,%5,%6,%7}, {%8,%9}, {%0,%1,%2,%3};"
                 : "+f"(c[0]), "+f"(c[1]), "+f"(c[2]), "+f"(c[3])
                 : "r"(a[0]), "r"(a[1]), "r"(a[2]), "r"(a[3]), "r"(b0), "r"(b1));
}

// ---------------- generic helpers ----------------
__device__ __forceinline__ float artanh_clip(float x) {
    const float lim = 1.0f - 1e-7f;
    x = fminf(fmaxf(x, -lim), lim);
    return atanhf(x);
}
__device__ __forceinline__ float blockReduceSum(float v) {
    __shared__ float sbuf[32];
    #pragma unroll
    for (int o = 16; o > 0; o >>= 1) v += __shfl_xor_sync(0xffffffffu, v, o);
    const int lane = threadIdx.x & 31;
    const int w    = threadIdx.x >> 5;
    if (lane == 0) sbuf[w] = v;
    __syncthreads();
    if (w == 0) {
        float t = (lane < 8) ? sbuf[lane] : 0.0f;
        #pragma unroll
        for (int o = 4; o > 0; o >>= 1) t += __shfl_xor_sync(0xffffffffu, t, o);
        if (lane == 0) sbuf[0] = t;
    }
    __syncthreads();
    float r = sbuf[0];
    __syncthreads();
    return r;
}
// split scaled value into fp16 hi/lo:  x*1024 = hi + lo (both fp16-normal)
__device__ __forceinline__ void split1h(float x, __half& h, __half& l) {
    const float xs = x * ASCALE;
    h = __float2half(xs);
    l = __float2half(xs - __half2float(h));
}

// ---------------- small kernels ----------------
__global__ __launch_bounds__(256)
void splitw_kernel(const float* __restrict__ W, __half* __restrict__ H) {
    const size_t i = (size_t)blockIdx.x * 256 + threadIdx.x;
    float4 v = reinterpret_cast<const float4*>(W)[i];
    __half2 a, b;
    a.x = __float2half(v.x); a.y = __float2half(v.y);
    b.x = __float2half(v.z); b.y = __float2half(v.w);
    reinterpret_cast<__half2*>(H)[i * 2 + 0] = a;
    reinterpret_cast<__half2*>(H)[i * 2 + 1] = b;
}

__global__ __launch_bounds__(256)
void splitx_kernel(const float* __restrict__ X, __half* __restrict__ H,
                   __half* __restrict__ L, float* __restrict__ xn) {
    const int t = threadIdx.x;
    const size_t base = (size_t)blockIdx.x * DIM;
    float4 v = reinterpret_cast<const float4*>(X + base)[t];
    float s = blockReduceSum(v.x * v.x + v.y * v.y + v.z * v.z + v.w * v.w);
    if (t == 0) xn[blockIdx.x] = fmaxf(sqrtf(s), MIN_NORM);
    __half h[4], l[4];
    split1h(v.x, h[0], l[0]); split1h(v.y, h[1], l[1]);
    split1h(v.z, h[2], l[2]); split1h(v.w, h[3], l[3]);
    __half2 h01; h01.x = h[0]; h01.y = h[1];
    __half2 h23; h23.x = h[2]; h23.y = h[3];
    __half2 l01; l01.x = l[0]; l01.y = l[1];
    __half2 l23; l23.x = l[2]; l23.y = l[3];
    reinterpret_cast<__half2*>(H + base)[t * 2 + 0] = h01;
    reinterpret_cast<__half2*>(H + base)[t * 2 + 1] = h23;
    reinterpret_cast<__half2*>(L + base)[t * 2 + 0] = l01;
    reinterpret_cast<__half2*>(L + base)[t * 2 + 1] = l23;
}

__global__ __launch_bounds__(256)
void bias_kernel(const float* __restrict__ b, int layer) {
    const int t = threadIdx.x;
    float4 v = reinterpret_cast<const float4*>(b)[t];
    float w0 = v.x, w1 = v.y, w2 = v.z, w3 = v.w;
    float s = blockReduceSum(w0*w0 + w1*w1 + w2*w2 + w3*w3);
    float n = fmaxf(sqrtf(s), MIN_NORM);
    float sc = tanhf(n) / n;
    w0 *= sc; w1 *= sc; w2 *= sc; w3 *= sc;
    float s2 = blockReduceSum(w0*w0 + w1*w1 + w2*w2 + w3*w3);
    float n2 = fmaxf(sqrtf(s2), MIN_NORM);
    if (n2 > MAXNORM) { float f = MAXNORM / n2; w0*=f; w1*=f; w2*=f; w3*=f; }
    float s3 = blockReduceSum(w0*w0 + w1*w1 + w2*w2 + w3*w3);
    reinterpret_cast<float4*>(g_hb[layer])[t] = make_float4(w0, w1, w2, w3);
    if (t == 0) g_y2[layer] = s3;
}

// ---------------- HMMA fp16x2 GEMM: C[m,n] = sum_k A[m,k]*B[n,k] ----------------
// A scaled by 1024 (hi+lo), B fp16; epilogue descales.
// SMEM chunk layout per array: chunk(row, c) at row*64 + ((c ^ ((row>>1)&3))*16)
// 3-stage cp.async pipeline, ONE __syncthreads per kt, B-fragment prefetch.
__global__ __launch_bounds__(256, 2)
void gemm2_kernel(const __half* __restrict__ Ah, const __half* __restrict__ Al,
                  const __half* __restrict__ B, float* __restrict__ C) {
    extern __shared__ char smem[];
    const uint32_t s32 = smem_u32(smem);

    const int tid = threadIdx.x;
    const int wid = tid >> 5;
    const int lid = tid & 31;
    const int m0 = blockIdx.y * BM;
    const int n0 = blockIdx.x * BN;
    const int warpM = (wid & 3) * 32;
    const int warpN = (wid >> 2) * 64;

    // ---- loader mapping: thread handles chunks i and i+256 of each array ----
    const int row0 = tid >> 2;           // 0..63
    const int cc   = tid & 3;
    const uint32_t off0 = (uint32_t)(row0 * 64 + ((cc ^ ((row0 >> 1) & 3)) * 16));
    const int row1 = row0 + 64;
    const uint32_t off1 = (uint32_t)(row1 * 64 + ((cc ^ ((row1 >> 1) & 3)) * 16));

    const __half* aH0 = Ah + (size_t)(m0 + row0) * DIM + cc * 8;
    const __half* aL0 = Al + (size_t)(m0 + row0) * DIM + cc * 8;
    const __half* b0  = B  + (size_t)(n0 + row0) * DIM + cc * 8;
    const size_t rstep = (size_t)64 * DIM;

    // ---- ldmatrix lane offsets ----
    uint32_t ofsA[2][2], ofsB[4][2];
    {
        const int lrow = (lid & 7) + ((lid >> 3) & 1) * 8;
        const int lchk = lid >> 4;       // 0/1
        #pragma unroll
        for (int mf = 0; mf < 2; ++mf)
            #pragma unroll
            for (int ks = 0; ks < 2; ++ks) {
                int r = warpM + mf * 16 + lrow;
                int c = 2 * ks + lchk;
                ofsA[mf][ks] = (uint32_t)(r * 64 + ((c ^ ((r >> 1) & 3)) * 16));
            }
        #pragma unroll
        for (int p = 0; p < 4; ++p)
            #pragma unroll
            for (int ks = 0; ks < 2; ++ks) {
                int r = warpN + p * 16 + lrow;
                int c = 2 * ks + lchk;
                ofsB[p][ks] = (uint32_t)(r * 64 + ((c ^ ((r >> 1) & 3)) * 16));
            }
    }

    float acc[2][8][4];
    #pragma unroll
    for (int i = 0; i < 2; ++i)
        #pragma unroll
        for (int j = 0; j < 8; ++j)
            #pragma unroll
            for (int q = 0; q < 4; ++q) acc[i][j][q] = 0.0f;

    auto issue = [&](int kt) {
        const uint32_t sb = s32 + (kt % STAGES) * STAGE_BYTES;
        const size_t ko = (size_t)kt * BKE;
        CP_ASYNC16(sb + ST_AH + off0, aH0 + ko);
        CP_ASYNC16(sb + ST_AH + off1, aH0 + rstep + ko);
        CP_ASYNC16(sb + ST_AL + off0, aL0 + ko);
        CP_ASYNC16(sb + ST_AL + off1, aL0 + rstep + ko);
        CP_ASYNC16(sb + ST_B  + off0, b0  + ko);
        CP_ASYNC16(sb + ST_B  + off1, b0  + rstep + ko);
    };

    // prologue: stages 0 and 1 in flight
    issue(0); CP_COMMIT();
    issue(1); CP_COMMIT();

    for (int kt = 0; kt < KITERS; ++kt) {
        CP_WAIT1();            // own group kt complete (<=1 pending)
        __syncthreads();       // everyone's group kt complete; stage (kt-1)%3 free

        const uint32_t sA = s32 + (kt % STAGES) * STAGE_BYTES;
        #pragma unroll
        for (int ks = 0; ks < 2; ++ks) {
            uint32_t ahf[2][4], alf[2][4];
            ldsm4(ahf[0], sA + ST_AH + ofsA[0][ks]);
            ldsm4(ahf[1], sA + ST_AH + ofsA[1][ks]);
            ldsm4(alf[0], sA + ST_AL + ofsA[0][ks]);
            ldsm4(alf[1], sA + ST_AL + ofsA[1][ks]);
            uint32_t bb[2][4];
            ldsm4(bb[0], sA + ST_B + ofsB[0][ks]);
            #pragma unroll
            for (int p = 0; p < 4; ++p) {
                const uint32_t* bh = bb[p & 1];
                if (p < 3) ldsm4(bb[(p + 1) & 1], sA + ST_B + ofsB[p + 1][ks]);
                #pragma unroll
                for (int mf = 0; mf < 2; ++mf) {
                    mma16816(acc[mf][2*p],   ahf[mf], bh[0], bh[2]);
                    mma16816(acc[mf][2*p],   alf[mf], bh[0], bh[2]);
                    mma16816(acc[mf][2*p+1], ahf[mf], bh[1], bh[3]);
                    mma16816(acc[mf][2*p+1], alf[mf], bh[1], bh[3]);
                }
            }
        }

        // refill the stage freed by the barrier above ((kt-1)%3 == (kt+2)%3)
        if (kt + 2 < KITERS) { issue(kt + 2); CP_COMMIT(); }
    }

    // ---- epilogue: descale + direct stores ----
    #pragma unroll
    for (int mf = 0; mf < 2; ++mf) {
        #pragma unroll
        for (int nf = 0; nf < 8; ++nf) {
            const int r   = m0 + warpM + mf * 16 + (lid >> 2);
            const int col = n0 + warpN + nf * 8 + (lid & 3) * 2;
            float2 v0 = make_float2(acc[mf][nf][0] * AISCALE, acc[mf][nf][1] * AISCALE);
            float2 v1 = make_float2(acc[mf][nf][2] * AISCALE, acc[mf][nf][3] * AISCALE);
            *reinterpret_cast<float2*>(&C[(size_t)r * DIM + col])       = v0;
            *reinterpret_cast<float2*>(&C[(size_t)(r + 8) * DIM + col]) = v1;
        }
    }
}

// ---------------- fused per-row epilogue ----------------
template<bool SPLIT>
__global__ __launch_bounds__(256)
void rowpost_kernel(const float* __restrict__ MX, const float* __restrict__ xnv,
                    float* __restrict__ OUT,
                    __half* __restrict__ OH, __half* __restrict__ OL,
                    float* __restrict__ xnout, int layer) {
    const int t = threadIdx.x;
    const size_t base = (size_t)blockIdx.x * DIM;

    float4 v = reinterpret_cast<const float4*>(MX + base)[t];
    float w[4] = {v.x, v.y, v.z, v.w};
    const float xn = xnv[blockIdx.x];

    // gyro_matvec tail
    float r1 = blockReduceSum(w[0]*w[0] + w[1]*w[1] + w[2]*w[2] + w[3]*w[3]);
    const bool allzero = (r1 == 0.0f);
    const float mxn = fmaxf(sqrtf(r1), MIN_NORM);
    const float arg = (mxn / xn) * artanh_clip(xn);
    float sres = tanhf(arg) / mxn;
    if (allzero) sres = 0.0f;
    #pragma unroll
    for (int i = 0; i < 4; ++i) w[i] *= sres;

    // proj
    {
        float s = blockReduceSum(w[0]*w[0] + w[1]*w[1] + w[2]*w[2] + w[3]*w[3]);
        float n = fmaxf(sqrtf(s), MIN_NORM);
        if (n > MAXNORM) { float f = MAXNORM / n; w[0]*=f; w[1]*=f; w[2]*=f; w[3]*=f; }
    }
    // gyro_add(hyp_bias)
    {
        float4 hv = reinterpret_cast<const float4*>(g_hb[layer])[t];
        float h[4] = {hv.x, hv.y, hv.z, hv.w};
        float x2 = blockReduceSum(w[0]*w[0] + w[1]*w[1] + w[2]*w[2] + w[3]*w[3]);
        float xy = blockReduceSum(w[0]*h[0] + w[1]*h[1] + w[2]*h[2] + w[3]*h[3]);
        float y2 = g_y2[layer];
        float alpha = 1.0f + 2.0f * xy + y2;
        float beta  = 1.0f - x2;
        float inv   = 1.0f / fmaxf(1.0f + 2.0f * xy + x2 * y2, MIN_NORM);
        #pragma unroll
        for (int i = 0; i < 4; ++i) w[i] = (alpha * w[i] + beta * h[i]) * inv;
    }
    // proj (end of hyp_linear)
    {
        float s = blockReduceSum(w[0]*w[0] + w[1]*w[1] + w[2]*w[2] + w[3]*w[3]);
        float n = fmaxf(sqrtf(s), MIN_NORM);
        if (n > MAXNORM) { float f = MAXNORM / n; w[0]*=f; w[1]*=f; w[2]*=f; w[3]*=f; }
    }
    // hyp_tanh_act: proj
    {
        float s = blockReduceSum(w[0]*w[0] + w[1]*w[1] + w[2]*w[2] + w[3]*w[3]);
        float n = fmaxf(sqrtf(s), MIN_NORM);
        if (n > MAXNORM) { float f = MAXNORM / n; w[0]*=f; w[1]*=f; w[2]*=f; w[3]*=f; }
    }
    // logmap0 + tanh
    {
        float s = blockReduceSum(w[0]*w[0] + w[1]*w[1] + w[2]*w[2] + w[3]*w[3]);
        float n = fmaxf(sqrtf(s), MIN_NORM);
        float sl = artanh_clip(n) / n;
        #pragma unroll
        for (int i = 0; i < 4; ++i) w[i] = tanhf(sl * w[i]);
    }
    // expmap0
    {
        float s = blockReduceSum(w[0]*w[0] + w[1]*w[1] + w[2]*w[2] + w[3]*w[3]);
        float tn = fmaxf(sqrtf(s), MIN_NORM);
        float se = tanhf(tn) / tn;
        #pragma unroll
        for (int i = 0; i < 4; ++i) w[i] *= se;
    }
    // final proj (+ next-layer norm)
    float nfin;
    {
        float s = blockReduceSum(w[0]*w[0] + w[1]*w[1] + w[2]*w[2] + w[3]*w[3]);
        float n = fmaxf(sqrtf(s), MIN_NORM);
        nfin = fminf(n, MAXNORM);
        if (n > MAXNORM) { float f = MAXNORM / n; w[0]*=f; w[1]*=f; w[2]*=f; w[3]*=f; }
    }

    if (SPLIT) {
        __half h[4], l[4];
        #pragma unroll
        for (int i = 0; i < 4; ++i) split1h(w[i], h[i], l[i]);
        __half2 h01; h01.x = h[0]; h01.y = h[1];
        __half2 h23; h23.x = h[2]; h23.y = h[3];
        __half2 l01; l01.x = l[0]; l01.y = l[1];
        __half2 l23; l23.x = l[2]; l23.y = l[3];
        reinterpret_cast<__half2*>(OH + base)[t * 2 + 0] = h01;
        reinterpret_cast<__half2*>(OH + base)[t * 2 + 1] = h23;
        reinterpret_cast<__half2*>(OL + base)[t * 2 + 0] = l01;
        reinterpret_cast<__half2*>(OL + base)[t * 2 + 1] = l23;
        if (t == 0) xnout[blockIdx.x] = fmaxf(nfin, MIN_NORM);
    } else {
        reinterpret_cast<float4*>(OUT + base)[t] = make_float4(w[0], w[1], w[2], w[3]);
    }
}

// ---------------- launch ----------------
extern "C" void kernel_launch(void* const* d_in, const int* in_sizes, int n_in,
                              void* d_out, int out_size) {
    const float* x  = (const float*)d_in[0];
    const float* W1 = (const float*)d_in[1];
    const float* b1 = (const float*)d_in[2];
    const float* W2 = (const float*)d_in[3];
    const float* b2 = (const float*)d_in[4];
    float* out = (float*)d_out;

    const int N = in_sizes[0] / DIM;

    float *mx = nullptr, *xn = nullptr;
    __half *ah, *al, *w1, *w2;
    cudaGetSymbolAddress((void**)&mx, g_mx);
    cudaGetSymbolAddress((void**)&xn, g_xn);
    cudaGetSymbolAddress((void**)&ah, g_ah);
    cudaGetSymbolAddress((void**)&al, g_al);
    cudaGetSymbolAddress((void**)&w1, g_w1);
    cudaGetSymbolAddress((void**)&w2, g_w2);

    cudaFuncSetAttribute(gemm2_kernel, cudaFuncAttributeMaxDynamicSharedMemorySize, SMEM_BYTES);

    const dim3 ggrid(DIM / BN, N / BM);
    const int wgrid = (DIM * DIM) / (4 * 256);

    splitw_kernel<<<wgrid, 256>>>(W1, w1);
    splitw_kernel<<<wgrid, 256>>>(W2, w2);
    bias_kernel<<<1, 256>>>(b1, 0);
    bias_kernel<<<1, 256>>>(b2, 1);

    // layer 1
    splitx_kernel<<<N, 256>>>(x, ah, al, xn);
    gemm2_kernel<<<ggrid, 256, SMEM_BYTES>>>(ah, al, w1, mx);
    rowpost_kernel<true><<<N, 256>>>(mx, xn, nullptr, ah, al, xn, 0);

    // layer 2
    gemm2_kernel<<<ggrid, 256, SMEM_BYTES>>>(ah, al, w2, out);
    rowpost_kernel<false><<<N, 256>>>(out, xn, out, nullptr, nullptr, nullptr, 1);
}

// round 7
// speedup vs baseline: 2.1175x; 1.4740x over previous
#include <cuda_runtime.h>
#include <cuda_fp16.h>
#include <math.h>
#include <stdint.h>

#define DIM 1024
#define NMAX 32768
#define MAXNORM (1.0f - 1e-5f)
#define MIN_NORM 1e-15f

// ---------------- GEMM tiling ----------------
#define BM 128
#define BN 128
#define BKE 32                     // fp16 k elements per stage (64 bytes per row)
#define KITERS (DIM / BKE)         // 32
#define STAGES 4
// per-stage layout: A 8KB | B 8KB
#define ST_A 0
#define ST_B 8192
#define STAGE_BYTES 16384
#define SMEM_BYTES (STAGES * STAGE_BYTES)   // 64KB, 2 CTAs/SM

// ---------------- scratch (device globals) ----------------
__device__ float   g_mx[(size_t)NMAX * DIM];   // fp32 GEMM output
__device__ __half  g_a[(size_t)NMAX * DIM];    // activations fp16
__device__ __half  g_w1[DIM * DIM];
__device__ __half  g_w2[DIM * DIM];
__device__ float   g_xn[NMAX];
__device__ float   g_hb[2][DIM];
__device__ float   g_y2[2];

// ---------------- PTX helpers ----------------
__device__ __forceinline__ uint32_t smem_u32(const void* p) {
    uint32_t a;
    asm("{ .reg .u64 t; cvta.to.shared.u64 t, %1; cvt.u32.u64 %0, t; }" : "=r"(a) : "l"(p));
    return a;
}
#define CP_ASYNC16(dst, src) \
    asm volatile("cp.async.cg.shared.global [%0], [%1], 16;" :: "r"(dst), "l"(src) : "memory")
#define CP_COMMIT() asm volatile("cp.async.commit_group;" ::: "memory")
#define CP_WAIT2()  asm volatile("cp.async.wait_group 2;" ::: "memory")

__device__ __forceinline__ void ldsm4(uint32_t* r, uint32_t addr) {
    asm volatile("ldmatrix.sync.aligned.m8n8.x4.shared.b16 {%0,%1,%2,%3}, [%4];"
                 : "=r"(r[0]), "=r"(r[1]), "=r"(r[2]), "=r"(r[3]) : "r"(addr));
}
__device__ __forceinline__ void mma16816(float* c, const uint32_t* a, uint32_t b0, uint32_t b1) {
    asm volatile("mma.sync.aligned.m16n8k16.row.col.f32.f16.f16.f32 "
                 "{%0,%1,%2,%3}, {%4,%5,%6,%7}, {%8,%9}, {%0,%1,%2,%3};"
                 : "+f"(c[0]), "+f"(c[1]), "+f"(c[2]), "+f"(c[3])
                 : "r"(a[0]), "r"(a[1]), "r"(a[2]), "r"(a[3]), "r"(b0), "r"(b1));
}

// ---------------- generic helpers ----------------
__device__ __forceinline__ float artanh_clip(float x) {
    const float lim = 1.0f - 1e-7f;
    x = fminf(fmaxf(x, -lim), lim);
    return atanhf(x);
}
__device__ __forceinline__ float blockReduceSum(float v) {
    __shared__ float sbuf[32];
    #pragma unroll
    for (int o = 16; o > 0; o >>= 1) v += __shfl_xor_sync(0xffffffffu, v, o);
    const int lane = threadIdx.x & 31;
    const int w    = threadIdx.x >> 5;
    if (lane == 0) sbuf[w] = v;
    __syncthreads();
    if (w == 0) {
        float t = (lane < 8) ? sbuf[lane] : 0.0f;
        #pragma unroll
        for (int o = 4; o > 0; o >>= 1) t += __shfl_xor_sync(0xffffffffu, t, o);
        if (lane == 0) sbuf[0] = t;
    }
    __syncthreads();
    float r = sbuf[0];
    __syncthreads();
    return r;
}

// ---------------- small kernels ----------------
// fp32 -> fp16 conversion (weights)
__global__ __launch_bounds__(256)
void cvtw_kernel(const float* __restrict__ W, __half* __restrict__ H) {
    const size_t i = (size_t)blockIdx.x * 256 + threadIdx.x;
    float4 v = reinterpret_cast<const float4*>(W)[i];
    __half2 a, b;
    a.x = __float2half(v.x); a.y = __float2half(v.y);
    b.x = __float2half(v.z); b.y = __float2half(v.w);
    reinterpret_cast<__half2*>(H)[i * 2 + 0] = a;
    reinterpret_cast<__half2*>(H)[i * 2 + 1] = b;
}

// activations: fp32 -> fp16 + row norm
__global__ __launch_bounds__(256)
void cvtx_kernel(const float* __restrict__ X, __half* __restrict__ H, float* __restrict__ xn) {
    const int t = threadIdx.x;
    const size_t base = (size_t)blockIdx.x * DIM;
    float4 v = reinterpret_cast<const float4*>(X + base)[t];
    float s = blockReduceSum(v.x * v.x + v.y * v.y + v.z * v.z + v.w * v.w);
    if (t == 0) xn[blockIdx.x] = fmaxf(sqrtf(s), MIN_NORM);
    __half2 a, b;
    a.x = __float2half(v.x); a.y = __float2half(v.y);
    b.x = __float2half(v.z); b.y = __float2half(v.w);
    reinterpret_cast<__half2*>(H + base)[t * 2 + 0] = a;
    reinterpret_cast<__half2*>(H + base)[t * 2 + 1] = b;
}

__global__ __launch_bounds__(256)
void bias_kernel(const float* __restrict__ b, int layer) {
    const int t = threadIdx.x;
    float4 v = reinterpret_cast<const float4*>(b)[t];
    float w0 = v.x, w1 = v.y, w2 = v.z, w3 = v.w;
    float s = blockReduceSum(w0*w0 + w1*w1 + w2*w2 + w3*w3);
    float n = fmaxf(sqrtf(s), MIN_NORM);
    float sc = tanhf(n) / n;
    w0 *= sc; w1 *= sc; w2 *= sc; w3 *= sc;
    float s2 = blockReduceSum(w0*w0 + w1*w1 + w2*w2 + w3*w3);
    float n2 = fmaxf(sqrtf(s2), MIN_NORM);
    if (n2 > MAXNORM) { float f = MAXNORM / n2; w0*=f; w1*=f; w2*=f; w3*=f; }
    float s3 = blockReduceSum(w0*w0 + w1*w1 + w2*w2 + w3*w3);
    reinterpret_cast<float4*>(g_hb[layer])[t] = make_float4(w0, w1, w2, w3);
    if (t == 0) g_y2[layer] = s3;
}

// ---------------- HMMA fp16 GEMM: C[m,n] = sum_k A[m,k]*B[n,k] (fp32 accum) ----------------
// SMEM chunk layout per array: chunk(row, c) at row*64 + ((c ^ ((row>>1)&3))*16)
// 4-stage cp.async pipeline, one __syncthreads per kt, B-fragment prefetch.
__global__ __launch_bounds__(256, 2)
void gemm1_kernel(const __half* __restrict__ A, const __half* __restrict__ B,
                  float* __restrict__ C) {
    extern __shared__ char smem[];
    const uint32_t s32 = smem_u32(smem);

    const int tid = threadIdx.x;
    const int wid = tid >> 5;
    const int lid = tid & 31;
    const int m0 = blockIdx.y * BM;
    const int n0 = blockIdx.x * BN;
    const int warpM = (wid & 3) * 32;
    const int warpN = (wid >> 2) * 64;

    // ---- loader mapping: thread handles chunks i and i+256 of each array ----
    const int row0 = tid >> 2;           // 0..63
    const int cc   = tid & 3;
    const uint32_t off0 = (uint32_t)(row0 * 64 + ((cc ^ ((row0 >> 1) & 3)) * 16));
    const int row1 = row0 + 64;
    const uint32_t off1 = (uint32_t)(row1 * 64 + ((cc ^ ((row1 >> 1) & 3)) * 16));

    const __half* a0 = A + (size_t)(m0 + row0) * DIM + cc * 8;
    const __half* b0 = B + (size_t)(n0 + row0) * DIM + cc * 8;
    const size_t rstep = (size_t)64 * DIM;

    // ---- ldmatrix lane offsets ----
    uint32_t ofsA[2][2], ofsB[4][2];
    {
        const int lrow = (lid & 7) + ((lid >> 3) & 1) * 8;
        const int lchk = lid >> 4;       // 0/1
        #pragma unroll
        for (int mf = 0; mf < 2; ++mf)
            #pragma unroll
            for (int ks = 0; ks < 2; ++ks) {
                int r = warpM + mf * 16 + lrow;
                int c = 2 * ks + lchk;
                ofsA[mf][ks] = (uint32_t)(r * 64 + ((c ^ ((r >> 1) & 3)) * 16));
            }
        #pragma unroll
        for (int p = 0; p < 4; ++p)
            #pragma unroll
            for (int ks = 0; ks < 2; ++ks) {
                int r = warpN + p * 16 + lrow;
                int c = 2 * ks + lchk;
                ofsB[p][ks] = (uint32_t)(r * 64 + ((c ^ ((r >> 1) & 3)) * 16));
            }
    }

    float acc[2][8][4];
    #pragma unroll
    for (int i = 0; i < 2; ++i)
        #pragma unroll
        for (int j = 0; j < 8; ++j)
            #pragma unroll
            for (int q = 0; q < 4; ++q) acc[i][j][q] = 0.0f;

    auto issue = [&](int kt) {
        const uint32_t sb = s32 + (kt % STAGES) * STAGE_BYTES;
        const size_t ko = (size_t)kt * BKE;
        CP_ASYNC16(sb + ST_A + off0, a0 + ko);
        CP_ASYNC16(sb + ST_A + off1, a0 + rstep + ko);
        CP_ASYNC16(sb + ST_B + off0, b0 + ko);
        CP_ASYNC16(sb + ST_B + off1, b0 + rstep + ko);
    };

    // prologue: stages 0..2 in flight
    issue(0); CP_COMMIT();
    issue(1); CP_COMMIT();
    issue(2); CP_COMMIT();

    for (int kt = 0; kt < KITERS; ++kt) {
        CP_WAIT2();            // own group kt complete (<=2 pending)
        __syncthreads();       // everyone's group kt complete; stage (kt-1)%4 free

        const uint32_t sA = s32 + (kt % STAGES) * STAGE_BYTES;
        #pragma unroll
        for (int ks = 0; ks < 2; ++ks) {
            uint32_t ahf[2][4];
            ldsm4(ahf[0], sA + ST_A + ofsA[0][ks]);
            ldsm4(ahf[1], sA + ST_A + ofsA[1][ks]);
            uint32_t bb[2][4];
            ldsm4(bb[0], sA + ST_B + ofsB[0][ks]);
            #pragma unroll
            for (int p = 0; p < 4; ++p) {
                const uint32_t* bh = bb[p & 1];
                if (p < 3) ldsm4(bb[(p + 1) & 1], sA + ST_B + ofsB[p + 1][ks]);
                #pragma unroll
                for (int mf = 0; mf < 2; ++mf) {
                    mma16816(acc[mf][2*p],   ahf[mf], bh[0], bh[2]);
                    mma16816(acc[mf][2*p+1], ahf[mf], bh[1], bh[3]);
                }
            }
        }

        // refill the stage freed by the barrier above ((kt-1)%4 == (kt+3)%4)
        if (kt + 3 < KITERS) { issue(kt + 3); CP_COMMIT(); }
    }

    // ---- epilogue: direct stores ----
    #pragma unroll
    for (int mf = 0; mf < 2; ++mf) {
        #pragma unroll
        for (int nf = 0; nf < 8; ++nf) {
            const int r   = m0 + warpM + mf * 16 + (lid >> 2);
            const int col = n0 + warpN + nf * 8 + (lid & 3) * 2;
            float2 v0 = make_float2(acc[mf][nf][0], acc[mf][nf][1]);
            float2 v1 = make_float2(acc[mf][nf][2], acc[mf][nf][3]);
            *reinterpret_cast<float2*>(&C[(size_t)r * DIM + col])       = v0;
            *reinterpret_cast<float2*>(&C[(size_t)(r + 8) * DIM + col]) = v1;
        }
    }
}

// ---------------- fused per-row epilogue ----------------
template<bool SPLIT>
__global__ __launch_bounds__(256)
void rowpost_kernel(const float* __restrict__ MX, const float* __restrict__ xnv,
                    float* __restrict__ OUT, __half* __restrict__ OH,
                    float* __restrict__ xnout, int layer) {
    const int t = threadIdx.x;
    const size_t base = (size_t)blockIdx.x * DIM;

    float4 v = reinterpret_cast<const float4*>(MX + base)[t];
    float w[4] = {v.x, v.y, v.z, v.w};
    const float xn = xnv[blockIdx.x];

    // gyro_matvec tail
    float r1 = blockReduceSum(w[0]*w[0] + w[1]*w[1] + w[2]*w[2] + w[3]*w[3]);
    const bool allzero = (r1 == 0.0f);
    const float mxn = fmaxf(sqrtf(r1), MIN_NORM);
    const float arg = (mxn / xn) * artanh_clip(xn);
    float sres = tanhf(arg) / mxn;
    if (allzero) sres = 0.0f;
    #pragma unroll
    for (int i = 0; i < 4; ++i) w[i] *= sres;

    // proj
    {
        float s = blockReduceSum(w[0]*w[0] + w[1]*w[1] + w[2]*w[2] + w[3]*w[3]);
        float n = fmaxf(sqrtf(s), MIN_NORM);
        if (n > MAXNORM) { float f = MAXNORM / n; w[0]*=f; w[1]*=f; w[2]*=f; w[3]*=f; }
    }
    // gyro_add(hyp_bias)
    {
        float4 hv = reinterpret_cast<const float4*>(g_hb[layer])[t];
        float h[4] = {hv.x, hv.y, hv.z, hv.w};
        float x2 = blockReduceSum(w[0]*w[0] + w[1]*w[1] + w[2]*w[2] + w[3]*w[3]);
        float xy = blockReduceSum(w[0]*h[0] + w[1]*h[1] + w[2]*h[2] + w[3]*h[3]);
        float y2 = g_y2[layer];
        float alpha = 1.0f + 2.0f * xy + y2;
        float beta  = 1.0f - x2;
        float inv   = 1.0f / fmaxf(1.0f + 2.0f * xy + x2 * y2, MIN_NORM);
        #pragma unroll
        for (int i = 0; i < 4; ++i) w[i] = (alpha * w[i] + beta * h[i]) * inv;
    }
    // proj (end of hyp_linear)
    {
        float s = blockReduceSum(w[0]*w[0] + w[1]*w[1] + w[2]*w[2] + w[3]*w[3]);
        float n = fmaxf(sqrtf(s), MIN_NORM);
        if (n > MAXNORM) { float f = MAXNORM / n; w[0]*=f; w[1]*=f; w[2]*=f; w[3]*=f; }
    }
    // hyp_tanh_act: proj
    {
        float s = blockReduceSum(w[0]*w[0] + w[1]*w[1] + w[2]*w[2] + w[3]*w[3]);
        float n = fmaxf(sqrtf(s), MIN_NORM);
        if (n > MAXNORM) { float f = MAXNORM / n; w[0]*=f; w[1]*=f; w[2]*=f; w[3]*=f; }
    }
    // logmap0 + tanh
    {
        float s = blockReduceSum(w[0]*w[0] + w[1]*w[1] + w[2]*w[2] + w[3]*w[3]);
        float n = fmaxf(sqrtf(s), MIN_NORM);
        float sl = artanh_clip(n) / n;
        #pragma unroll
        for (int i = 0; i < 4; ++i) w[i] = tanhf(sl * w[i]);
    }
    // expmap0
    {
        float s = blockReduceSum(w[0]*w[0] + w[1]*w[1] + w[2]*w[2] + w[3]*w[3]);
        float tn = fmaxf(sqrtf(s), MIN_NORM);
        float se = tanhf(tn) / tn;
        #pragma unroll
        for (int i = 0; i < 4; ++i) w[i] *= se;
    }
    // final proj (+ next-layer norm)
    float nfin;
    {
        float s = blockReduceSum(w[0]*w[0] + w[1]*w[1] + w[2]*w[2] + w[3]*w[3]);
        float n = fmaxf(sqrtf(s), MIN_NORM);
        nfin = fminf(n, MAXNORM);
        if (n > MAXNORM) { float f = MAXNORM / n; w[0]*=f; w[1]*=f; w[2]*=f; w[3]*=f; }
    }

    if (SPLIT) {
        __half2 a, b;
        a.x = __float2half(w[0]); a.y = __float2half(w[1]);
        b.x = __float2half(w[2]); b.y = __float2half(w[3]);
        reinterpret_cast<__half2*>(OH + base)[t * 2 + 0] = a;
        reinterpret_cast<__half2*>(OH + base)[t * 2 + 1] = b;
        if (t == 0) xnout[blockIdx.x] = fmaxf(nfin, MIN_NORM);
    } else {
        reinterpret_cast<float4*>(OUT + base)[t] = make_float4(w[0], w[1], w[2], w[3]);
    }
}

// ---------------- launch ----------------
extern "C" void kernel_launch(void* const* d_in, const int* in_sizes, int n_in,
                              void* d_out, int out_size) {
    const float* x  = (const float*)d_in[0];
    const float* W1 = (const float*)d_in[1];
    const float* b1 = (const float*)d_in[2];
    const float* W2 = (const float*)d_in[3];
    const float* b2 = (const float*)d_in[4];
    float* out = (float*)d_out;

    const int N = in_sizes[0] / DIM;

    float *mx = nullptr, *xn = nullptr;
    __half *a, *w1, *w2;
    cudaGetSymbolAddress((void**)&mx, g_mx);
    cudaGetSymbolAddress((void**)&xn, g_xn);
    cudaGetSymbolAddress((void**)&a,  g_a);
    cudaGetSymbolAddress((void**)&w1, g_w1);
    cudaGetSymbolAddress((void**)&w2, g_w2);

    cudaFuncSetAttribute(gemm1_kernel, cudaFuncAttributeMaxDynamicSharedMemorySize, SMEM_BYTES);

    const dim3 ggrid(DIM / BN, N / BM);
    const int wgrid = (DIM * DIM) / (4 * 256);

    cvtw_kernel<<<wgrid, 256>>>(W1, w1);
    cvtw_kernel<<<wgrid, 256>>>(W2, w2);
    bias_kernel<<<1, 256>>>(b1, 0);
    bias_kernel<<<1, 256>>>(b2, 1);

    // layer 1
    cvtx_kernel<<<N, 256>>>(x, a, xn);
    gemm1_kernel<<<ggrid, 256, SMEM_BYTES>>>(a, w1, mx);
    rowpost_kernel<true><<<N, 256>>>(mx, xn, nullptr, a, xn, 0);

    // layer 2
    gemm1_kernel<<<ggrid, 256, SMEM_BYTES>>>(a, w2, out);
    rowpost_kernel<false><<<N, 256>>>(out, xn, out, nullptr, nullptr, 1);
}